// round 11
// baseline (speedup 1.0000x reference)
#include <cuda_runtime.h>
#include <float.h>
#include <math.h>
#include <stdint.h>

// CropRoi: f (4,64,32,32,32) f32; proposals (96,8) f32; out (96,64,7,7,7) f32.
// Box: c0 = max(floor((c-s/2)/4),0), c1 = min(ceil((c+s/2)/4),32); L in [2,13].
// Adaptive windows per axis: size 1..3, always in-range -> plain max.
//
// One warp per (n, c, d-bin i): 43008 short independent warps; each does ~13
// full-row LDGs (lane = w-in-row, one 128B line = 1 L1 wavefront) feeding 7
// independent j-accumulators, then 21 shuffles resolve the w-bins and lanes
// 0..6 store 7 consecutive floats. All bounds warp-uniform (no divergence).
//
// R10 bugfix: w-taps are packed BOX-RELATIVE (lane l holds w = c0w + l), and
// the lane load address is clamped to the row end (no OOB; duplicates of the
// last element are never tap sources since taps <= Lw-1 <= 31-c0w).

#define RBINS 7
#define FDIM 32
#define MAXN 128

__device__ int      g_base[MAXN];        // f element offset of box corner, ch0
__device__ uint64_t g_hwin[MAXN];        // 7 x (hs:4 | he:4)
__device__ uint64_t g_dwin[MAXN];        // 7 x (ds:4 | de:4)
__device__ int      g_wtap[MAXN * 8];    // per k: rel taps t0 | t1<<8 | t2<<16
__device__ int      g_wclamp[MAXN];      // 31 - c0w (max lane offset in row)

__global__ void precompute_kernel(const float* __restrict__ props)
{
    const int n = blockIdx.x;
    const int o = threadIdx.x;
    const float* p = props + n * 8;

    int c0[3], L[3];
#pragma unroll
    for (int ax = 0; ax < 3; ++ax) {
        const float ce = p[2 + ax], si = p[5 + ax];
        int lo = (int)floorf((ce - si * 0.5f) * 0.25f);
        int hi = (int)ceilf ((ce + si * 0.5f) * 0.25f);
        lo = max(lo, 0); hi = min(hi, FDIM);
        c0[ax] = lo;
        L[ax]  = max(hi - lo, 0);
    }

    if (o == 0) {
        const int b = (int)p[0];
        g_base[n] = ((b * 64) << 15) +
                    ((c0[0] * FDIM + c0[1]) * FDIM + c0[2]);
        g_wclamp[n] = (FDIM - 1) - c0[2];
        uint64_t hw = 0, dw = 0;
        for (int j = 0; j < RBINS; ++j) {
            const int hs = (j * L[1]) / RBINS;
            const int he = ((j + 1) * L[1] + RBINS - 1) / RBINS;
            hw |= (uint64_t)(hs | (he << 4)) << (8 * j);
            const int ds = (j * L[0]) / RBINS;
            const int de = ((j + 1) * L[0] + RBINS - 1) / RBINS;
            dw |= (uint64_t)(ds | (de << 4)) << (8 * j);
        }
        g_hwin[n] = hw;
        g_dwin[n] = dw;
    }

    if (o < RBINS) {
        // BOX-RELATIVE taps: lane l holds w = c0w + l
        const int s = (o * L[2]) / RBINS;
        const int e = ((o + 1) * L[2] + RBINS - 1) / RBINS;
        const int t0 = s;
        const int t1 = min(s + 1, e - 1);
        const int t2 = e - 1;
        g_wtap[n * 8 + o] = t0 | (t1 << 8) | (t2 << 16);
    }
}

__global__ __launch_bounds__(256)
void pool_kernel(const float* __restrict__ f, float* __restrict__ out)
{
    const int n    = blockIdx.x;
    const int lane = threadIdx.x & 31;
    const int warp = threadIdx.x >> 5;           // 0..7
    const int s    = blockIdx.y * 8 + warp;      // 0..447
    const int c    = s / RBINS;                  // channel 0..63
    const int i    = s - c * RBINS;              // d-bin 0..6

    const uint64_t dw = g_dwin[n];
    const int ds = (int)(dw >> (8 * i))     & 15;
    const int de = (int)(dw >> (8 * i + 4)) & 15;
    const uint64_t hw = g_hwin[n];

    const int wt = g_wtap[n * 8 + min(lane, RBINS - 1)];
    const int t0 =  wt        & 255;
    const int t1 = (wt >>  8) & 255;
    const int t2 = (wt >> 16) & 255;

    const int lw = min(lane, g_wclamp[n]);       // stay inside the 32-wide row
    const float* src = f + g_base[n] + (c << 15) + lw;

    float acc[RBINS];
#pragma unroll
    for (int j = 0; j < RBINS; ++j) acc[j] = -FLT_MAX;

    for (int d = ds; d < de; ++d) {              // 1..3, warp-uniform
        const float* rowd = src + (d << 10);
#pragma unroll
        for (int j = 0; j < RBINS; ++j) {        // 7 independent chains
            const int hs = (int)(hw >> (8 * j))     & 15;
            const int he = (int)(hw >> (8 * j + 4)) & 15;
            for (int h = hs; h < he; ++h)        // 1..3, warp-uniform
                acc[j] = fmaxf(acc[j], __ldg(rowd + (h << 5)));  // 1 wavefront
        }
    }

    float* ob = out + ((size_t)(n * 64 + c) * 343 + i * 49) + lane;
#pragma unroll
    for (int j = 0; j < RBINS; ++j) {
        const float g = fmaxf(fmaxf(__shfl_sync(0xFFFFFFFFu, acc[j], t0),
                                    __shfl_sync(0xFFFFFFFFu, acc[j], t1)),
                              __shfl_sync(0xFFFFFFFFu, acc[j], t2));
        if (lane < RBINS)
            ob[j * RBINS] = g;                   // 7 consecutive floats
    }
}

extern "C" void kernel_launch(void* const* d_in, const int* in_sizes, int n_in,
                              void* d_out, int out_size)
{
    const float* f     = (const float*)d_in[0];
    const float* props = (const float*)d_in[2];
    float* out = (float*)d_out;

    const int N = in_sizes[2] / 8;   // 96

    precompute_kernel<<<N, 32>>>(props);
    pool_kernel<<<dim3(N, 56), 256>>>(f, out);   // 56*8 = 448 = 64 ch * 7 d-bins
}

// round 12
// speedup vs baseline: 1.6171x; 1.6171x over previous
#include <cuda_runtime.h>
#include <float.h>
#include <math.h>

// CropRoi: f (4,64,32,32,32) f32; proposals (96,8) f32; out (96,64,7,7,7) f32.
// Box: c0 = max(floor((c-s/2)/4),0), c1 = min(ceil((c+s/2)/4),32); L in [2,13].
// Adaptive windows per axis: size 1..3, always in-range -> plain max.
//
// Best measured shape = R2 (thread-per-bin, grid 96x64): 23.3us, with issue
// dominated by divergent-loop machinery (~165 warp-instr vs ~40 useful).
// This round: identical layout + BRANCHLESS warp-uniform loops. Each warp
// reduces its lanes' window sizes (__reduce_max_sync) and iterates the warp-
// max volume with per-lane clamped offsets (min(d,nd) etc). Same iteration
// count the divergent loop already paid, same wavefronts (clamped duplicates
// coalesce onto already-touched lines), but ~6 instr/iter instead of ~18.

#define RBINS 7
#define NBINS 343
#define FDIM 32
#define MAXN 128

__device__ int g_desc[MAXN * NBINS];
__device__ int g_base[MAXN];

__global__ void precompute_kernel(const float* __restrict__ props)
{
    const int n = blockIdx.x;
    const int o = threadIdx.x;
    const float* p = props + n * 8;

    int c0[3], L[3];
#pragma unroll
    for (int ax = 0; ax < 3; ++ax) {
        const float ce = p[2 + ax], si = p[5 + ax];
        int lo = (int)floorf((ce - si * 0.5f) * 0.25f);
        int hi = (int)ceilf ((ce + si * 0.5f) * 0.25f);
        lo = max(lo, 0); hi = min(hi, FDIM);
        c0[ax] = lo;
        L[ax]  = max(hi - lo, 0);
    }

    if (o == 0) {
        const int b = (int)p[0];
        g_base[n] = ((b * 64) << 15) +
                    ((c0[0] * FDIM + c0[1]) * FDIM + c0[2]);
    }

    if (o < NBINS) {
        const int k = o % RBINS;
        const int j = (o / RBINS) % RBINS;
        const int i = o / (RBINS * RBINS);

        const int ds = (i * L[0]) / RBINS, de = ((i + 1) * L[0] + RBINS - 1) / RBINS;
        const int hs = (j * L[1]) / RBINS, he = ((j + 1) * L[1] + RBINS - 1) / RBINS;
        const int ws = (k * L[2]) / RBINS, we = ((k + 1) * L[2] + RBINS - 1) / RBINS;

        const int start = (ds * FDIM + hs) * FDIM + ws;                 // 15 bits
        const int nd = de - ds - 1, nh = he - hs - 1, nw = we - ws - 1; // 0..2
        g_desc[n * NBINS + o] = start | (nd << 15) | (nh << 17) | (nw << 19);
    }
}

__global__ __launch_bounds__(352)
void pool_kernel(const float* __restrict__ f, float* __restrict__ out)
{
    const int n = blockIdx.x;   // proposal
    const int c = blockIdx.y;   // channel
    const int tid = threadIdx.x;
    const int t = min(tid, NBINS - 1);     // tail lanes shadow bin 342 (no store)

    const int desc  = g_desc[n * NBINS + t];
    const int start =  desc        & 0x7FFF;
    const int nd    = (desc >> 15) & 3;
    const int nh    = (desc >> 17) & 3;
    const int nw    = (desc >> 19) & 3;

    // warp-uniform trip counts (what the divergent loop paid anyway)
    const int ndw = __reduce_max_sync(0xFFFFFFFFu, nd);
    const int nhw = __reduce_max_sync(0xFFFFFFFFu, nh);
    const int nww = __reduce_max_sync(0xFFFFFFFFu, nw);

    const float* base = f + g_base[n] + (c << 15) + start;

    // branchless clamped-tap loops: per-lane offset min(x, nx); duplicates
    // coalesce onto lines this warp already touches -> no extra wavefronts
    float m = -FLT_MAX;
    for (int d = 0; d <= ndw; ++d) {
        const int doff = min(d, nd) << 10;
        for (int h = 0; h <= nhw; ++h) {
            const int hoff = doff + (min(h, nh) << 5);
            for (int w = 0; w <= nww; ++w)
                m = fmaxf(m, __ldg(base + hoff + min(w, nw)));
        }
    }

    if (tid < NBINS)
        out[(size_t)(n * 64 + c) * NBINS + tid] = m;
}

extern "C" void kernel_launch(void* const* d_in, const int* in_sizes, int n_in,
                              void* d_out, int out_size)
{
    const float* f     = (const float*)d_in[0];
    const float* props = (const float*)d_in[2];
    float* out = (float*)d_out;

    const int N = in_sizes[2] / 8;   // 96

    precompute_kernel<<<N, 352>>>(props);
    pool_kernel<<<dim3(N, 64), 352>>>(f, out);
}

// round 13
// speedup vs baseline: 1.7193x; 1.0632x over previous
#include <cuda_runtime.h>
#include <float.h>
#include <math.h>

// CropRoi: f (4,64,32,32,32) f32; proposals (96,8) f32; out (96,64,7,7,7) f32.
// Box: c0 = max(floor((c-s/2)/4),0), c1 = min(ceil((c+s/2)/4),32); L in [1,14].
// Adaptive windows per axis: size 1..3, always in-range -> plain max; clamped
// duplicate taps {s, min(s+1,e-1), e-1} are harmless under max.
//
// Warp per (n,c), separable 3-stage pool, straight-line 3-tap everywhere:
//  Phase A: for j(7, unrolled) x d(Ld): 3 clamped h-tap ROW loads (lane = w,
//           each = ONE 128B line = ONE L1 wavefront) + 2 fmax; 3 tap-shuffles
//           resolve all 7 w-bins at once; lanes 0..6 STS pyr[d][j][k].
//  Phase B: same warp (__syncwarp only): 343 outputs, 3 clamped d-tap LDS
//           each, coalesced STG.
// Blocks span 8 different proposals (n = octet*8 + warp) -> balanced blocks.
// All tap tables packed & pre-shifted by a tiny precompute kernel.

#define RBINS 7
#define FDIM 32
#define MAXN 128
#define PYR_STRIDE 640              // 13*49 = 637, padded

__device__ int2 g_meta[MAXN];       // x = base elem offset (ch0), y = Ld
__device__ int  g_wtap[MAXN * 8];   // abs w taps: t0 | t1<<8 | t2<<16 (lane idx)
__device__ int  g_htap[MAXN * 8];   // per j, preshifted: (h<<5) 3 x 10 bits
__device__ int  g_dtap[MAXN * 8];   // per i, premultiplied: (d*49) 3 x 10 bits

__global__ void precompute_kernel(const float* __restrict__ props)
{
    const int n = blockIdx.x;
    const int o = threadIdx.x;
    const float* p = props + n * 8;

    int c0[3], L[3];
#pragma unroll
    for (int ax = 0; ax < 3; ++ax) {
        const float ce = p[2 + ax], si = p[5 + ax];
        int lo = (int)floorf((ce - si * 0.5f) * 0.25f);
        int hi = (int)ceilf ((ce + si * 0.5f) * 0.25f);
        lo = max(lo, 0); hi = min(hi, FDIM);
        c0[ax] = lo;
        L[ax]  = max(hi - lo, 1);
    }

    if (o == 0) {
        const int b = (int)p[0];
        g_meta[n] = make_int2(((b * 64) << 15) +
                              ((c0[0] * FDIM + c0[1]) * FDIM),  // corner (d,h), w=0
                              L[0]);
    }

    if (o < RBINS) {
        // w taps: absolute lane indices (lane l holds w = l)
        {
            const int s = (o * L[2]) / RBINS;
            const int e = ((o + 1) * L[2] + RBINS - 1) / RBINS;
            const int t0 = c0[2] + s;
            const int t1 = c0[2] + min(s + 1, e - 1);
            const int t2 = c0[2] + e - 1;
            g_wtap[n * 8 + o] = t0 | (t1 << 8) | (t2 << 16);
        }
        // h taps: relative to c0h, preshifted by <<5 (row stride)
        {
            const int s = (o * L[1]) / RBINS;
            const int e = ((o + 1) * L[1] + RBINS - 1) / RBINS;
            const int a = s << 5;
            const int b2 = min(s + 1, e - 1) << 5;
            const int c2 = (e - 1) << 5;
            g_htap[n * 8 + o] = a | (b2 << 10) | (c2 << 20);
        }
        // d taps: relative, premultiplied by 49 (pyr d-stride)
        {
            const int s = (o * L[0]) / RBINS;
            const int e = ((o + 1) * L[0] + RBINS - 1) / RBINS;
            const int a = s * 49;
            const int b2 = min(s + 1, e - 1) * 49;
            const int c2 = (e - 1) * 49;
            g_dtap[n * 8 + o] = a | (b2 << 10) | (c2 << 20);
        }
    }
}

__global__ __launch_bounds__(256)
void pool_kernel(const float* __restrict__ f, float* __restrict__ out, int N)
{
    const int blk   = blockIdx.x;
    const int c     = blk & 63;            // channel
    const int octet = blk >> 6;            // proposal octet
    const int lane  = threadIdx.x & 31;
    const int wp    = threadIdx.x >> 5;    // 0..7
    const int n     = octet * 8 + wp;      // proposal (block spans 8 proposals)
    if (n >= N) return;

    __shared__ float pyr_s[8 * PYR_STRIDE];    // 20480 B
    float* P = pyr_s + wp * PYR_STRIDE;

    const int2 meta = g_meta[n];
    const int  Ld   = meta.y;
    const float* src = f + meta.x + (c << 15) + lane;   // lane = absolute w

    const int wt = g_wtap[n * 8 + min(lane, RBINS - 1)];
    const int t0 =  wt        & 255;
    const int t1 = (wt >>  8) & 255;
    const int t2 =  wt >> 16;

    // ---- Phase A: pyr[d][j][k] = max over h-window(j), w-window(k) of row d
#pragma unroll
    for (int j = 0; j < RBINS; ++j) {
        const int ht = g_htap[n * 8 + j];
        const int o0 =  ht        & 1023;
        const int o1 = (ht >> 10) & 1023;
        const int o2 =  ht >> 20;

        const float* rp = src;
        int idx = j * RBINS + lane;
        for (int d = 0; d < Ld; ++d) {
            // 3 row loads: every lane on the SAME 128B line -> 1 wavefront each
            const float v = fmaxf(fmaxf(__ldg(rp + o0), __ldg(rp + o1)),
                                  __ldg(rp + o2));
            // resolve all 7 w-bins with 3 tap shuffles
            const float g = fmaxf(fmaxf(__shfl_sync(0xFFFFFFFFu, v, t0),
                                        __shfl_sync(0xFFFFFFFFu, v, t1)),
                                  __shfl_sync(0xFFFFFFFFu, v, t2));
            if (lane < RBINS) P[idx] = g;
            rp  += FDIM * FDIM;
            idx += 49;
        }
    }

    __syncwarp();

    // ---- Phase B: pool over d with 3 clamped d-taps, coalesced stores
    float* ob = out + (size_t)(n * 64 + c) * 343;
#pragma unroll
    for (int t = 0; t < 11; ++t) {
        const int o = t * 32 + lane;
        if (o < 343) {
            const int i = o / 49;                  // const div -> mul/shift
            const int r = o - i * 49;              // j*7 + k
            const int dt = g_dtap[n * 8 + i];
            const float m = fmaxf(fmaxf(P[r + ( dt        & 1023)],
                                        P[r + ((dt >> 10) & 1023)]),
                                  P[r + ( dt >> 20)]);
            ob[o] = m;
        }
    }
}

extern "C" void kernel_launch(void* const* d_in, const int* in_sizes, int n_in,
                              void* d_out, int out_size)
{
    const float* f     = (const float*)d_in[0];
    const float* props = (const float*)d_in[2];
    float* out = (float*)d_out;

    const int N = in_sizes[2] / 8;           // 96
    const int octets = (N + 7) / 8;          // 12

    precompute_kernel<<<N, 32>>>(props);
    pool_kernel<<<octets * 64, 256>>>(f, out, N);
}